// round 9
// baseline (speedup 1.0000x reference)
#include <cuda_runtime.h>
#include <cuda_fp16.h>
#include <cstdint>

// ---------------- problem constants ----------------
#define NODES   262144
#define BGRAPH  1024
#define NPG     256
#define HID     192
#define HID2    384
#define NEDGE   4194304
#define KKEEP   231
#define LN_EPS  1e-5f

// exact power-of-2 scaling keeps all fp16 split terms in normal range
#define XSCALE  256.0f          // A pre-scale (2^8)
#define WSCALE  2048.0f         // B pre-scale (2^11)
#define DESCALE (1.0f / 524288.0f)   // 2^-19

// ---------------- head tiling ----------------
#define MTILE   64             // nodes per CTA
#define KSTEPS  12             // K = 192 in chunks of 16
#define NTHREAD 512            // 16 warps: 4 (M) x 4 (N), warp tile 16 x 96
// B split global: [kstep 12][split 2][n 384][16 fp16]
#define B_CHUNK_BYTES  24576   // 2*384*16*2
__device__ __align__(16) unsigned char d_Bsplit[12 * B_CHUNK_BYTES];
__device__ float2        d_klg[NODES];      // {keep, logit} packed
__device__ unsigned char d_touched[NODES];

// ---------------- smem layout ----------------
#define A_PITCH   200                    // fp16/row (odd multiple of 8 -> ldsm conflict-free)
#define A_SPLIT_B (MTILE * A_PITCH * 2)  // 25600 B per split
#define OFF_A     0                      // 2 * 25600 = 51200
#define OFF_B     51200                  // 2 * 24576 = 49152 (double buffer)
#define OFF_PAR   100352                 // b1|gamma|beta|w2 : 4*384*4 = 6144
#define OFF_RS1   106496                 // [64][4] floats = 1024
#define OFF_RS2   107520                 // 1024
#define OFF_RT    108544                 // 1024
#define SMEM_REQ  109568

// ---------------- PTX helpers (sm_80-era, safe for compute_103) ----------
__device__ __forceinline__ uint32_t smem_u32(const void* p) {
    uint32_t a;
    asm("{ .reg .u64 t; cvta.to.shared.u64 t, %1; cvt.u32.u64 %0, t; }"
        : "=r"(a) : "l"(p));
    return a;
}
__device__ __forceinline__ void ldsm4(uint32_t* r, uint32_t a) {
    asm volatile("ldmatrix.sync.aligned.m8n8.x4.shared.b16 {%0,%1,%2,%3}, [%4];"
                 : "=r"(r[0]), "=r"(r[1]), "=r"(r[2]), "=r"(r[3]) : "r"(a));
}
__device__ __forceinline__ void mma16816(float* d, const uint32_t* a, const uint32_t* b) {
    asm volatile("mma.sync.aligned.m16n8k16.row.col.f32.f16.f16.f32 "
                 "{%0,%1,%2,%3}, {%4,%5,%6,%7}, {%8,%9}, {%0,%1,%2,%3};"
                 : "+f"(d[0]), "+f"(d[1]), "+f"(d[2]), "+f"(d[3])
                 : "r"(a[0]), "r"(a[1]), "r"(a[2]), "r"(a[3]),
                   "r"(b[0]), "r"(b[1]));
}
#define CPASYNC16(dst, src) asm volatile("cp.async.cg.shared.global [%0], [%1], 16;" :: "r"(dst), "l"(src))
#define CPCOMMIT()          asm volatile("cp.async.commit_group;" ::: "memory")
#define CPWAIT(n)           asm volatile("cp.async.wait_group %0;" :: "n"(n) : "memory")

// ---------------------------------------------------------------------------
// Prologue: 2-way fp16 split of W1^T * 2^11 (B[n][k] = W1[k][n] * WSCALE):
//   offset = ks*24576 + s*12288 + n*32 + (k&15)*2
// ---------------------------------------------------------------------------
__global__ void __launch_bounds__(256)
wsplit_kernel(const float* __restrict__ W1)
{
    int idx = blockIdx.x * 256 + threadIdx.x;      // 73728 = 288 * 256
    int n = idx % HID2, k = idx / HID2;
    float x = W1[k * HID2 + n] * WSCALE;
    __half s1 = __float2half_rn(x);
    float r1 = x - __half2float(s1);
    __half s2 = __float2half_rn(r1);

    uint32_t base = (uint32_t)(k >> 4) * B_CHUNK_BYTES + (uint32_t)n * 32u
                  + (uint32_t)(k & 15) * 2u;
    *(__half*)(d_Bsplit + base)         = s1;
    *(__half*)(d_Bsplit + base + 12288) = s2;
}

// no-op launches: keep head_kernel at captured launch slot #4 for ncu
__global__ void dummy_kernel() {}

// ---------------------------------------------------------------------------
// Head: 64 nodes x 384 cols per CTA; 16 warps (4 M x 4 N), warp tile 16x96.
// 4-term fp16 2x2-split HMMA (exact to ~2^-24); b-split-major term order;
// fused b1 + LayerNorm + ReLU + dot(W2) epilogue with 2^-19 descale.
// 4 warps/SMSP for latency hiding; mainloop regs ~110 < 127 cap (no spills).
// ---------------------------------------------------------------------------
__global__ void __launch_bounds__(NTHREAD, 1)
head_kernel(const float* __restrict__ h, const float* __restrict__ g,
            const float* __restrict__ b1, const float* __restrict__ lngamma,
            const float* __restrict__ lnbeta, const float* __restrict__ W2,
            const float* __restrict__ b2, float* __restrict__ logits)
{
    extern __shared__ char sm[];
    const uint32_t sb = smem_u32(sm);

    const int tid  = threadIdx.x;
    const int wid  = tid >> 5;
    const int lane = tid & 31;
    const int wr   = wid & 3;            // M-warp (4), 16 rows each
    const int wc   = wid >> 2;           // N-warp (4), 96 cols each
    const int n0   = blockIdx.x * MTILE;
    const float b2v = __ldg(b2);

    // ---- params -> smem ----
    {
        float* par = (float*)(sm + OFF_PAR);
        if (tid < HID2) {
            par[tid]            = b1[tid];
            par[HID2 + tid]     = lngamma[tid];
            par[2 * HID2 + tid] = lnbeta[tid];
            par[3 * HID2 + tid] = W2[tid];
        }
    }

    // ---- A build: x = (h + g[graph]) * 2^8, 2-way fp16 split -> smem ----
    {
        const float2* h2p = (const float2*)h;
        const int gbase = (n0 >> 8) * HID;
        for (int i = tid; i < MTILE * 96; i += NTHREAD) {   // col-pairs
            int row = i / 96, cp = i % 96;
            float2 hv = h2p[(n0 + row) * 96 + cp];
            int c0 = cp * 2;
            float x0 = (hv.x + __ldg(&g[gbase + c0]))     * XSCALE;
            float x1 = (hv.y + __ldg(&g[gbase + c0 + 1])) * XSCALE;

            __half a0 = __float2half_rn(x0), e0 = __float2half_rn(x1);
            float ra = x0 - __half2float(a0), rb = x1 - __half2float(e0);
            __half a1 = __float2half_rn(ra), e1 = __float2half_rn(rb);

            uint32_t p0 = ((uint32_t)__half_as_ushort(e0) << 16) | __half_as_ushort(a0);
            uint32_t p1 = ((uint32_t)__half_as_ushort(e1) << 16) | __half_as_ushort(a1);

            uint32_t off = (uint32_t)row * (A_PITCH * 2) + (uint32_t)c0 * 2u;
            *(uint32_t*)(sm + OFF_A + off)             = p0;
            *(uint32_t*)(sm + OFF_A + A_SPLIT_B + off) = p1;
        }
    }

    // ---- cp.async B chunk 0 into buffer 0 ----
    {
        const char* src = (const char*)d_Bsplit;
        for (int i = tid; i < B_CHUNK_BYTES / 16; i += NTHREAD)
            CPASYNC16(sb + OFF_B + i * 16, src + i * 16);
        CPCOMMIT();
    }

    // ---- ldmatrix addresses ----
    // A .x4 (16x16 row-major frag): quad q: rows +(q&1)*8, cols k0 +(q>>1)*8
    const int q = lane >> 3;
    const uint32_t aRowByte =
        (uint32_t)(wr * 16 + (lane & 7) + ((q & 1) << 3)) * (A_PITCH * 2);
    const uint32_t aColByte = (uint32_t)((q >> 1) << 3) * 2;
    uint32_t aAddr[2];
#pragma unroll
    for (int s = 0; s < 2; s++)
        aAddr[s] = sb + OFF_A + (uint32_t)s * A_SPLIT_B + aRowByte + aColByte;
    // B .x4 covers an nt-pair (16 n-rows x k16):
    //   lanes 0-7: rows 0-7 @k0 | 8-15: rows 0-7 @k8 | 16-23: rows 8-15 @k0 | 24-31: rows 8-15 @k8
    const uint32_t bRow  = (uint32_t)((lane & 7) + ((lane >> 4) << 3));
    const uint32_t bLane = ((uint32_t)wc * 96u + bRow) * 32u
                         + (uint32_t)((lane >> 3) & 1) * 16u;

    float acc[12][4];
#pragma unroll
    for (int nt = 0; nt < 12; nt++)
#pragma unroll
        for (int j = 0; j < 4; j++) acc[nt][j] = 0.f;

    // ---- main loop: 12 k-steps, double-buffered B ----
    for (int ks = 0; ks < KSTEPS; ks++) {
        __syncthreads();                 // reads of buf[(ks+1)&1] (iter ks-1) done
        if (ks + 1 < KSTEPS) {
            const char* src = (const char*)(d_Bsplit + (uint32_t)(ks + 1) * B_CHUNK_BYTES);
            const uint32_t dst = sb + OFF_B + (uint32_t)((ks + 1) & 1) * B_CHUNK_BYTES;
            for (int i = tid; i < B_CHUNK_BYTES / 16; i += NTHREAD)
                CPASYNC16(dst + i * 16, src + i * 16);
            CPCOMMIT();
            CPWAIT(1);
        } else {
            CPWAIT(0);
        }
        __syncthreads();                 // buf[ks&1] visible to all warps

        const uint32_t kOff = (uint32_t)ks * 32u;
        uint32_t Afr[2][4];
#pragma unroll
        for (int s = 0; s < 2; s++)
            ldsm4(Afr[s], aAddr[s] + kOff);

        const uint32_t bBase = sb + OFF_B + (uint32_t)(ks & 1) * B_CHUNK_BYTES + bLane;

#pragma unroll
        for (int sbp = 0; sbp < 2; sbp++) {          // b-split major
            uint32_t Bfr[12][2];
#pragma unroll
            for (int p = 0; p < 6; p++) {            // 6 nt-pairs (96 cols)
                uint32_t r[4];
                ldsm4(r, bBase + (uint32_t)sbp * 12288u + (uint32_t)p * 512u);
                Bfr[2 * p][0] = r[0]; Bfr[2 * p][1] = r[1];
                Bfr[2 * p + 1][0] = r[2]; Bfr[2 * p + 1][1] = r[3];
            }
#pragma unroll
            for (int sa = 0; sa < 2; sa++)           // acc chains 12 apart
#pragma unroll
                for (int nt = 0; nt < 12; nt++)
                    mma16816(acc[nt], Afr[sa], Bfr[nt]);
        }
    }

    // ---- epilogue: descale, +b1, LN stats, LN+ReLU+dot(W2) ----
    const float* par = (const float*)(sm + OFF_PAR);
    float* rs1 = (float*)(sm + OFF_RS1);
    float* rs2 = (float*)(sm + OFF_RS2);
    float* rt  = (float*)(sm + OFF_RT);
    const int l4 = lane >> 2, lm = lane & 3;

#pragma unroll
    for (int hf = 0; hf < 2; hf++) {
        float s1 = 0.f, s2 = 0.f;
#pragma unroll
        for (int nt = 0; nt < 12; nt++) {
            const int cb = wc * 96 + nt * 8 + 2 * lm;
            float2 bv = *(const float2*)&par[cb];
            float v0 = acc[nt][2 * hf]     * DESCALE + bv.x;
            float v1 = acc[nt][2 * hf + 1] * DESCALE + bv.y;
            s1 += v0 + v1; s2 += v0 * v0 + v1 * v1;
        }
        s1 += __shfl_xor_sync(0xffffffffu, s1, 1);
        s1 += __shfl_xor_sync(0xffffffffu, s1, 2);
        s2 += __shfl_xor_sync(0xffffffffu, s2, 1);
        s2 += __shfl_xor_sync(0xffffffffu, s2, 2);
        if (lm == 0) {
            const int row = wr * 16 + hf * 8 + l4;
            rs1[row * 4 + wc] = s1;
            rs2[row * 4 + wc] = s2;
        }
    }
    __syncthreads();

#pragma unroll
    for (int hf = 0; hf < 2; hf++) {
        const int row = wr * 16 + hf * 8 + l4;
        const float S1 = rs1[row * 4] + rs1[row * 4 + 1] + rs1[row * 4 + 2] + rs1[row * 4 + 3];
        const float S2 = rs2[row * 4] + rs2[row * 4 + 1] + rs2[row * 4 + 2] + rs2[row * 4 + 3];
        const float mu  = S1 * (1.0f / HID2);
        const float var = S2 * (1.0f / HID2) - mu * mu;
        const float inv = rsqrtf(var + LN_EPS);
        float t = 0.f;
#pragma unroll
        for (int nt = 0; nt < 12; nt++) {
            const int cb = wc * 96 + nt * 8 + 2 * lm;
            float2 bv = *(const float2*)&par[cb];
            float2 gm = *(const float2*)&par[HID2 + cb];
            float2 bt = *(const float2*)&par[2 * HID2 + cb];
            float2 w2 = *(const float2*)&par[3 * HID2 + cb];
            float v0 = acc[nt][2 * hf]     * DESCALE + bv.x;
            float v1 = acc[nt][2 * hf + 1] * DESCALE + bv.y;
            float z0 = fmaxf((v0 - mu) * inv * gm.x + bt.x, 0.f);
            float z1 = fmaxf((v1 - mu) * inv * gm.y + bt.y, 0.f);
            t += z0 * w2.x + z1 * w2.y;
        }
        t += __shfl_xor_sync(0xffffffffu, t, 1);
        t += __shfl_xor_sync(0xffffffffu, t, 2);
        if (lm == 0) rt[row * 4 + wc] = t;
    }
    __syncthreads();
    if (tid < MTILE)
        logits[n0 + tid] = rt[tid * 4] + rt[tid * 4 + 1] + rt[tid * 4 + 2]
                         + rt[tid * 4 + 3] + b2v;
}

// ---------------------------------------------------------------------------
// Exact per-graph top-k (jax tie semantics); writes packed {keep, logit};
// zeroes touched[].
// ---------------------------------------------------------------------------
__global__ void __launch_bounds__(256)
topk_kernel(const float* __restrict__ logits)
{
    __shared__ float sv[NPG];
    const int node = blockIdx.x * NPG + threadIdx.x;
    const int t = threadIdx.x;
    const float v = logits[node];
    sv[t] = v;
    d_touched[node] = 0;
    __syncthreads();
    int rank = 0;
#pragma unroll 8
    for (int j = 0; j < NPG; j++) {
        const float u = sv[j];
        rank += (u > v) || (u == v && j < t);
    }
    d_klg[node] = make_float2((rank < KKEEP) ? 1.0f : 0.0f, v);
}

// ---------------------------------------------------------------------------
// Edge masking + weights + touched flags (4 edges / thread, packed gathers)
// ---------------------------------------------------------------------------
__global__ void __launch_bounds__(256)
edge_kernel(const int* __restrict__ ei,
            float* __restrict__ em, float* __restrict__ ew)
{
    const int idx = blockIdx.x * 256 + threadIdx.x;
    const int4 s = ((const int4*)ei)[idx];
    const int4 d = ((const int4*)(ei + NEDGE))[idx];

    const float2 sx = d_klg[s.x], dx = d_klg[d.x];
    const float2 sy = d_klg[s.y], dy = d_klg[d.y];
    const float2 sz = d_klg[s.z], dz = d_klg[d.z];
    const float2 sw = d_klg[s.w], dw = d_klg[d.w];

    float4 m, w;
    m.x = sx.x * dx.x;  w.x = (sx.y + dx.y) * m.x;
    m.y = sy.x * dy.x;  w.y = (sy.y + dy.y) * m.y;
    m.z = sz.x * dz.x;  w.z = (sz.y + dz.y) * m.z;
    m.w = sw.x * dw.x;  w.w = (sw.y + dw.y) * m.w;

    ((float4*)em)[idx] = m;
    ((float4*)ew)[idx] = w;

    if (m.x != 0.f) { d_touched[s.x] = 1; d_touched[d.x] = 1; }
    if (m.y != 0.f) { d_touched[s.y] = 1; d_touched[d.y] = 1; }
    if (m.z != 0.f) { d_touched[s.z] = 1; d_touched[d.z] = 1; }
    if (m.w != 0.f) { d_touched[s.w] = 1; d_touched[d.w] = 1; }
}

__global__ void __launch_bounds__(256)
mask_kernel(float* __restrict__ nm)
{
    const int i = blockIdx.x * 256 + threadIdx.x;
    nm[i] = d_touched[i] ? 1.0f : 0.0f;
}

// ---------------------------------------------------------------------------
// Launch: outputs concatenated f32: edge_mask | edge_weight | logits | node_mask
// head_kernel is launch #4 (ncu capture slot).
// ---------------------------------------------------------------------------
extern "C" void kernel_launch(void* const* d_in, const int* in_sizes, int n_in,
                              void* d_out, int out_size)
{
    const float* h       = (const float*)d_in[0];
    const float* g       = (const float*)d_in[1];
    const int*   ei      = (const int*)  d_in[2];
    const float* W1      = (const float*)d_in[3];
    const float* b1      = (const float*)d_in[4];
    const float* lngamma = (const float*)d_in[5];
    const float* lnbeta  = (const float*)d_in[6];
    const float* W2      = (const float*)d_in[7];
    const float* b2      = (const float*)d_in[8];

    float* out = (float*)d_out;
    float* em = out;
    float* ew = out + (size_t)NEDGE;
    float* lg = out + 2 * (size_t)NEDGE;
    float* nm = lg + NODES;

    cudaFuncSetAttribute(head_kernel,
                         cudaFuncAttributeMaxDynamicSharedMemorySize, SMEM_REQ);

    wsplit_kernel<<<(HID * HID2) / 256, 256>>>(W1);        // #1
    dummy_kernel<<<1, 32>>>();                              // #2
    dummy_kernel<<<1, 32>>>();                              // #3
    head_kernel<<<NODES / MTILE, NTHREAD, SMEM_REQ>>>(      // #4  <- ncu slot
        h, g, b1, lngamma, lnbeta, W2, b2, lg);
    topk_kernel<<<BGRAPH, 256>>>(lg);                       // #5
    edge_kernel<<<NEDGE / 1024, 256>>>(ei, em, ew);         // #6
    mask_kernel<<<NODES / 256, 256>>>(nm);                  // #7
}

// round 10
// speedup vs baseline: 1.0770x; 1.0770x over previous
#include <cuda_runtime.h>
#include <cuda_fp16.h>
#include <cstdint>

// ---------------- problem constants ----------------
#define NODES   262144
#define BGRAPH  1024
#define NPG     256
#define HID     192
#define HID2    384
#define NEDGE   4194304
#define KKEEP   231
#define LN_EPS  1e-5f

// exact power-of-2 scaling keeps all fp16 split terms in normal range
#define XSCALE  256.0f          // A pre-scale (2^8)
#define WSCALE  2048.0f         // B pre-scale (2^11)
#define DESCALE (1.0f / 524288.0f)   // 2^-19

// ---------------- head tiling ----------------
#define MTILE   64             // nodes per CTA
#define KSTEPS  12             // K = 192 in chunks of 16
#define NTHREAD 512            // 16 warps: 4 (M) x 4 (N), warp tile 16 x 96
// B split global: [kstep 12][split 2][n 384][16 fp16]
#define B_CHUNK_BYTES  24576   // 2*384*16*2
__device__ __align__(16) unsigned char d_Bsplit[12 * B_CHUNK_BYTES];
__device__ float2        d_klg[NODES];      // {keep, logit} packed
__device__ unsigned char d_touched[NODES];

// ---------------- smem layout ----------------
#define A_PITCH   200                    // fp16/row (odd multiple of 8 -> ldsm conflict-free)
#define A_SPLIT_B (MTILE * A_PITCH * 2)  // 25600 B per split
#define OFF_A     0                      // 2 * 25600 = 51200
#define OFF_B     51200                  // 2 * 24576 = 49152 (double buffer)
#define OFF_PAR   100352                 // b1|gamma|beta|w2 : 4*384*4 = 6144
#define OFF_RS1   106496                 // [64][4] floats = 1024
#define OFF_RS2   107520                 // 1024
#define OFF_RT    108544                 // 1024
#define SMEM_REQ  109568

// ---------------- PTX helpers (sm_80-era, safe for compute_103) ----------
__device__ __forceinline__ uint32_t smem_u32(const void* p) {
    uint32_t a;
    asm("{ .reg .u64 t; cvta.to.shared.u64 t, %1; cvt.u32.u64 %0, t; }"
        : "=r"(a) : "l"(p));
    return a;
}
__device__ __forceinline__ void ldsm4(uint32_t* r, uint32_t a) {
    asm volatile("ldmatrix.sync.aligned.m8n8.x4.shared.b16 {%0,%1,%2,%3}, [%4];"
                 : "=r"(r[0]), "=r"(r[1]), "=r"(r[2]), "=r"(r[3]) : "r"(a));
}
__device__ __forceinline__ void mma16816(float* d, const uint32_t* a, const uint32_t* b) {
    asm volatile("mma.sync.aligned.m16n8k16.row.col.f32.f16.f16.f32 "
                 "{%0,%1,%2,%3}, {%4,%5,%6,%7}, {%8,%9}, {%0,%1,%2,%3};"
                 : "+f"(d[0]), "+f"(d[1]), "+f"(d[2]), "+f"(d[3])
                 : "r"(a[0]), "r"(a[1]), "r"(a[2]), "r"(a[3]),
                   "r"(b[0]), "r"(b[1]));
}
#define CPASYNC16(dst, src) asm volatile("cp.async.cg.shared.global [%0], [%1], 16;" :: "r"(dst), "l"(src))
#define CPCOMMIT()          asm volatile("cp.async.commit_group;" ::: "memory")
#define CPWAIT(n)           asm volatile("cp.async.wait_group %0;" :: "n"(n) : "memory")

// ---------------------------------------------------------------------------
// Prologue: 2-way fp16 split of W1^T * 2^11 (B[n][k] = W1[k][n] * WSCALE):
//   offset = ks*24576 + s*12288 + n*32 + (k&15)*2
// ---------------------------------------------------------------------------
__global__ void __launch_bounds__(256)
wsplit_kernel(const float* __restrict__ W1)
{
    int idx = blockIdx.x * 256 + threadIdx.x;      // 73728 = 288 * 256
    int n = idx % HID2, k = idx / HID2;
    float x = W1[k * HID2 + n] * WSCALE;
    __half s1 = __float2half_rn(x);
    float r1 = x - __half2float(s1);
    __half s2 = __float2half_rn(r1);

    uint32_t base = (uint32_t)(k >> 4) * B_CHUNK_BYTES + (uint32_t)n * 32u
                  + (uint32_t)(k & 15) * 2u;
    *(__half*)(d_Bsplit + base)         = s1;
    *(__half*)(d_Bsplit + base + 12288) = s2;
}

// no-op launches: keep head_kernel at captured launch slot #4 for ncu
__global__ void dummy_kernel() {}

// ---------------------------------------------------------------------------
// Head: 64 nodes x 384 cols per CTA; 16 warps (4 M x 4 N), warp tile 16x96.
// 3-term fp16 2x2-split HMMA (a1b1 + a2b1 + a1b2; dropped a2b2 term is
// ~1e-8 relative -- far below fp32 accumulation noise). b-split-major order;
// fused b1 + LayerNorm + ReLU + dot(W2) epilogue with 2^-19 descale.
// 4 warps/SMSP; mainloop live set ~105 regs < 127 cap (no spills).
// ---------------------------------------------------------------------------
__global__ void __launch_bounds__(NTHREAD, 1)
head_kernel(const float* __restrict__ h, const float* __restrict__ g,
            const float* __restrict__ b1, const float* __restrict__ lngamma,
            const float* __restrict__ lnbeta, const float* __restrict__ W2,
            const float* __restrict__ b2, float* __restrict__ logits)
{
    extern __shared__ char sm[];
    const uint32_t sb = smem_u32(sm);

    const int tid  = threadIdx.x;
    const int wid  = tid >> 5;
    const int lane = tid & 31;
    const int wr   = wid & 3;            // M-warp (4), 16 rows each
    const int wc   = wid >> 2;           // N-warp (4), 96 cols each
    const int n0   = blockIdx.x * MTILE;
    const float b2v = __ldg(b2);

    // ---- params -> smem ----
    {
        float* par = (float*)(sm + OFF_PAR);
        if (tid < HID2) {
            par[tid]            = b1[tid];
            par[HID2 + tid]     = lngamma[tid];
            par[2 * HID2 + tid] = lnbeta[tid];
            par[3 * HID2 + tid] = W2[tid];
        }
    }

    // ---- A build: x = (h + g[graph]) * 2^8, 2-way fp16 split -> smem ----
    {
        const float2* h2p = (const float2*)h;
        const int gbase = (n0 >> 8) * HID;
        for (int i = tid; i < MTILE * 96; i += NTHREAD) {   // col-pairs
            int row = i / 96, cp = i % 96;
            float2 hv = h2p[(n0 + row) * 96 + cp];
            int c0 = cp * 2;
            float x0 = (hv.x + __ldg(&g[gbase + c0]))     * XSCALE;
            float x1 = (hv.y + __ldg(&g[gbase + c0 + 1])) * XSCALE;

            __half a0 = __float2half_rn(x0), e0 = __float2half_rn(x1);
            float ra = x0 - __half2float(a0), rb = x1 - __half2float(e0);
            __half a1 = __float2half_rn(ra), e1 = __float2half_rn(rb);

            uint32_t p0 = ((uint32_t)__half_as_ushort(e0) << 16) | __half_as_ushort(a0);
            uint32_t p1 = ((uint32_t)__half_as_ushort(e1) << 16) | __half_as_ushort(a1);

            uint32_t off = (uint32_t)row * (A_PITCH * 2) + (uint32_t)c0 * 2u;
            *(uint32_t*)(sm + OFF_A + off)             = p0;
            *(uint32_t*)(sm + OFF_A + A_SPLIT_B + off) = p1;
        }
    }

    // ---- cp.async B chunk 0 into buffer 0 ----
    {
        const char* src = (const char*)d_Bsplit;
        for (int i = tid; i < B_CHUNK_BYTES / 16; i += NTHREAD)
            CPASYNC16(sb + OFF_B + i * 16, src + i * 16);
        CPCOMMIT();
    }

    // ---- ldmatrix addresses ----
    // A .x4 (16x16 row-major frag): quad q: rows +(q&1)*8, cols k0 +(q>>1)*8
    const int q = lane >> 3;
    const uint32_t aRowByte =
        (uint32_t)(wr * 16 + (lane & 7) + ((q & 1) << 3)) * (A_PITCH * 2);
    const uint32_t aColByte = (uint32_t)((q >> 1) << 3) * 2;
    uint32_t aAddr[2];
#pragma unroll
    for (int s = 0; s < 2; s++)
        aAddr[s] = sb + OFF_A + (uint32_t)s * A_SPLIT_B + aRowByte + aColByte;
    // B .x4 covers an nt-pair (16 n-rows x k16):
    //   lanes 0-7: rows 0-7 @k0 | 8-15: rows 0-7 @k8 | 16-23: rows 8-15 @k0 | 24-31: rows 8-15 @k8
    const uint32_t bRow  = (uint32_t)((lane & 7) + ((lane >> 4) << 3));
    const uint32_t bLane = ((uint32_t)wc * 96u + bRow) * 32u
                         + (uint32_t)((lane >> 3) & 1) * 16u;

    float acc[12][4];
#pragma unroll
    for (int nt = 0; nt < 12; nt++)
#pragma unroll
        for (int j = 0; j < 4; j++) acc[nt][j] = 0.f;

    // ---- main loop: 12 k-steps, double-buffered B ----
    for (int ks = 0; ks < KSTEPS; ks++) {
        __syncthreads();                 // reads of buf[(ks+1)&1] (iter ks-1) done
        if (ks + 1 < KSTEPS) {
            const char* src = (const char*)(d_Bsplit + (uint32_t)(ks + 1) * B_CHUNK_BYTES);
            const uint32_t dst = sb + OFF_B + (uint32_t)((ks + 1) & 1) * B_CHUNK_BYTES;
            for (int i = tid; i < B_CHUNK_BYTES / 16; i += NTHREAD)
                CPASYNC16(dst + i * 16, src + i * 16);
            CPCOMMIT();
            CPWAIT(1);
        } else {
            CPWAIT(0);
        }
        __syncthreads();                 // buf[ks&1] visible to all warps

        const uint32_t kOff = (uint32_t)ks * 32u;
        uint32_t Afr[2][4];
#pragma unroll
        for (int s = 0; s < 2; s++)
            ldsm4(Afr[s], aAddr[s] + kOff);

        const uint32_t bBase = sb + OFF_B + (uint32_t)(ks & 1) * B_CHUNK_BYTES + bLane;

        {
            uint32_t Bfr[12][2];
            // ---- b-split 0: terms a1b1 and a2b1 ----
#pragma unroll
            for (int p = 0; p < 6; p++) {            // 6 nt-pairs (96 cols)
                uint32_t r[4];
                ldsm4(r, bBase + (uint32_t)p * 512u);
                Bfr[2 * p][0] = r[0]; Bfr[2 * p][1] = r[1];
                Bfr[2 * p + 1][0] = r[2]; Bfr[2 * p + 1][1] = r[3];
            }
#pragma unroll
            for (int sa = 0; sa < 2; sa++)           // acc chains 12 apart
#pragma unroll
                for (int nt = 0; nt < 12; nt++)
                    mma16816(acc[nt], Afr[sa], Bfr[nt]);

            // ---- b-split 1: term a1b2 only (a2b2 dropped, ~1e-8 rel) ----
#pragma unroll
            for (int p = 0; p < 6; p++) {
                uint32_t r[4];
                ldsm4(r, bBase + 12288u + (uint32_t)p * 512u);
                Bfr[2 * p][0] = r[0]; Bfr[2 * p][1] = r[1];
                Bfr[2 * p + 1][0] = r[2]; Bfr[2 * p + 1][1] = r[3];
            }
#pragma unroll
            for (int nt = 0; nt < 12; nt++)
                mma16816(acc[nt], Afr[0], Bfr[nt]);
        }
    }

    // ---- epilogue: descale, +b1, LN stats, LN+ReLU+dot(W2) ----
    const float* par = (const float*)(sm + OFF_PAR);
    float* rs1 = (float*)(sm + OFF_RS1);
    float* rs2 = (float*)(sm + OFF_RS2);
    float* rt  = (float*)(sm + OFF_RT);
    const int l4 = lane >> 2, lm = lane & 3;

#pragma unroll
    for (int hf = 0; hf < 2; hf++) {
        float s1 = 0.f, s2 = 0.f;
#pragma unroll
        for (int nt = 0; nt < 12; nt++) {
            const int cb = wc * 96 + nt * 8 + 2 * lm;
            float2 bv = *(const float2*)&par[cb];
            float v0 = acc[nt][2 * hf]     * DESCALE + bv.x;
            float v1 = acc[nt][2 * hf + 1] * DESCALE + bv.y;
            s1 += v0 + v1; s2 += v0 * v0 + v1 * v1;
        }
        s1 += __shfl_xor_sync(0xffffffffu, s1, 1);
        s1 += __shfl_xor_sync(0xffffffffu, s1, 2);
        s2 += __shfl_xor_sync(0xffffffffu, s2, 1);
        s2 += __shfl_xor_sync(0xffffffffu, s2, 2);
        if (lm == 0) {
            const int row = wr * 16 + hf * 8 + l4;
            rs1[row * 4 + wc] = s1;
            rs2[row * 4 + wc] = s2;
        }
    }
    __syncthreads();

#pragma unroll
    for (int hf = 0; hf < 2; hf++) {
        const int row = wr * 16 + hf * 8 + l4;
        const float S1 = rs1[row * 4] + rs1[row * 4 + 1] + rs1[row * 4 + 2] + rs1[row * 4 + 3];
        const float S2 = rs2[row * 4] + rs2[row * 4 + 1] + rs2[row * 4 + 2] + rs2[row * 4 + 3];
        const float mu  = S1 * (1.0f / HID2);
        const float var = S2 * (1.0f / HID2) - mu * mu;
        const float inv = rsqrtf(var + LN_EPS);
        float t = 0.f;
#pragma unroll
        for (int nt = 0; nt < 12; nt++) {
            const int cb = wc * 96 + nt * 8 + 2 * lm;
            float2 bv = *(const float2*)&par[cb];
            float2 gm = *(const float2*)&par[HID2 + cb];
            float2 bt = *(const float2*)&par[2 * HID2 + cb];
            float2 w2 = *(const float2*)&par[3 * HID2 + cb];
            float v0 = acc[nt][2 * hf]     * DESCALE + bv.x;
            float v1 = acc[nt][2 * hf + 1] * DESCALE + bv.y;
            float z0 = fmaxf((v0 - mu) * inv * gm.x + bt.x, 0.f);
            float z1 = fmaxf((v1 - mu) * inv * gm.y + bt.y, 0.f);
            t += z0 * w2.x + z1 * w2.y;
        }
        t += __shfl_xor_sync(0xffffffffu, t, 1);
        t += __shfl_xor_sync(0xffffffffu, t, 2);
        if (lm == 0) rt[row * 4 + wc] = t;
    }
    __syncthreads();
    if (tid < MTILE)
        logits[n0 + tid] = rt[tid * 4] + rt[tid * 4 + 1] + rt[tid * 4 + 2]
                         + rt[tid * 4 + 3] + b2v;
}

// ---------------------------------------------------------------------------
// Exact per-graph top-k (jax tie semantics); writes packed {keep, logit};
// zeroes touched[].
// ---------------------------------------------------------------------------
__global__ void __launch_bounds__(256)
topk_kernel(const float* __restrict__ logits)
{
    __shared__ float sv[NPG];
    const int node = blockIdx.x * NPG + threadIdx.x;
    const int t = threadIdx.x;
    const float v = logits[node];
    sv[t] = v;
    d_touched[node] = 0;
    __syncthreads();
    int rank = 0;
#pragma unroll 8
    for (int j = 0; j < NPG; j++) {
        const float u = sv[j];
        rank += (u > v) || (u == v && j < t);
    }
    d_klg[node] = make_float2((rank < KKEEP) ? 1.0f : 0.0f, v);
}

// ---------------------------------------------------------------------------
// Edge masking + weights + touched flags (4 edges / thread, packed gathers)
// ---------------------------------------------------------------------------
__global__ void __launch_bounds__(256)
edge_kernel(const int* __restrict__ ei,
            float* __restrict__ em, float* __restrict__ ew)
{
    const int idx = blockIdx.x * 256 + threadIdx.x;
    const int4 s = ((const int4*)ei)[idx];
    const int4 d = ((const int4*)(ei + NEDGE))[idx];

    const float2 sx = d_klg[s.x], dx = d_klg[d.x];
    const float2 sy = d_klg[s.y], dy = d_klg[d.y];
    const float2 sz = d_klg[s.z], dz = d_klg[d.z];
    const float2 sw = d_klg[s.w], dw = d_klg[d.w];

    float4 m, w;
    m.x = sx.x * dx.x;  w.x = (sx.y + dx.y) * m.x;
    m.y = sy.x * dy.x;  w.y = (sy.y + dy.y) * m.y;
    m.z = sz.x * dz.x;  w.z = (sz.y + dz.y) * m.z;
    m.w = sw.x * dw.x;  w.w = (sw.y + dw.y) * m.w;

    ((float4*)em)[idx] = m;
    ((float4*)ew)[idx] = w;

    if (m.x != 0.f) { d_touched[s.x] = 1; d_touched[d.x] = 1; }
    if (m.y != 0.f) { d_touched[s.y] = 1; d_touched[d.y] = 1; }
    if (m.z != 0.f) { d_touched[s.z] = 1; d_touched[d.z] = 1; }
    if (m.w != 0.f) { d_touched[s.w] = 1; d_touched[d.w] = 1; }
}

__global__ void __launch_bounds__(256)
mask_kernel(float* __restrict__ nm)
{
    const int i = blockIdx.x * 256 + threadIdx.x;
    nm[i] = d_touched[i] ? 1.0f : 0.0f;
}

// ---------------------------------------------------------------------------
// Launch: outputs concatenated f32: edge_mask | edge_weight | logits | node_mask
// head_kernel is launch #4 (ncu capture slot).
// ---------------------------------------------------------------------------
extern "C" void kernel_launch(void* const* d_in, const int* in_sizes, int n_in,
                              void* d_out, int out_size)
{
    const float* h       = (const float*)d_in[0];
    const float* g       = (const float*)d_in[1];
    const int*   ei      = (const int*)  d_in[2];
    const float* W1      = (const float*)d_in[3];
    const float* b1      = (const float*)d_in[4];
    const float* lngamma = (const float*)d_in[5];
    const float* lnbeta  = (const float*)d_in[6];
    const float* W2      = (const float*)d_in[7];
    const float* b2      = (const float*)d_in[8];

    float* out = (float*)d_out;
    float* em = out;
    float* ew = out + (size_t)NEDGE;
    float* lg = out + 2 * (size_t)NEDGE;
    float* nm = lg + NODES;

    cudaFuncSetAttribute(head_kernel,
                         cudaFuncAttributeMaxDynamicSharedMemorySize, SMEM_REQ);

    wsplit_kernel<<<(HID * HID2) / 256, 256>>>(W1);        // #1
    dummy_kernel<<<1, 32>>>();                              // #2
    dummy_kernel<<<1, 32>>>();                              // #3
    head_kernel<<<NODES / MTILE, NTHREAD, SMEM_REQ>>>(      // #4  <- ncu slot
        h, g, b1, lngamma, lnbeta, W2, b2, lg);
    topk_kernel<<<BGRAPH, 256>>>(lg);                       // #5
    edge_kernel<<<NEDGE / 1024, 256>>>(ei, em, ew);         // #6
    mask_kernel<<<NODES / 256, 256>>>(nm);                  // #7
}

// round 11
// speedup vs baseline: 1.6112x; 1.4960x over previous
#include <cuda_runtime.h>
#include <cuda_fp16.h>
#include <cstdint>

// ---------------- problem constants ----------------
#define NODES   262144
#define BGRAPH  1024
#define NPG     256
#define HID     192
#define HID2    384
#define NEDGE   4194304
#define KKEEP   231
#define LN_EPS  1e-5f

// exact power-of-2 scaling keeps all fp16 split terms in normal range
#define XSCALE  256.0f          // A pre-scale (2^8)
#define WSCALE  2048.0f         // B pre-scale (2^11)
#define DESCALE (1.0f / 524288.0f)   // 2^-19

// ---------------- head tiling ----------------
#define MTILE   64             // nodes per CTA
#define KSTEPS  12             // K = 192 in chunks of 16
#define NTHREAD 256            // 8 warps: 2 (M) x 4 (N), warp tile 32 x 96

// B in mma-fragment layout: [ks 12][wc 4][sbp 2][p 6][lane 32][reg 4] u32
// u32 index = ks*12288 + wc*3072 + sbp*1536 + p*256 + lane*8 ... (see wsplit)
__device__ __align__(16) uint32_t d_Bfrag[147456];
__device__ float2        d_klg[NODES];      // {keep, logit} packed
__device__ unsigned char d_touched[NODES];

// ---------------- smem layout ----------------
#define A_PITCH   200                    // fp16/row (odd multiple of 8 -> ldsm conflict-free)
#define A_SPLIT_B (MTILE * A_PITCH * 2)  // 25600 B per split
#define OFF_A     0                      // 2 * 25600 = 51200
#define OFF_PAR   51200                  // b1|gamma|beta|w2 : 4*384*4 = 6144
#define OFF_RS1   57344                  // [64][4] floats = 1024
#define OFF_RS2   58368                  // 1024
#define OFF_RT    59392                  // 1024
#define SMEM_REQ  60416

// ---------------- PTX helpers (sm_80-era, safe for compute_103) ----------
__device__ __forceinline__ uint32_t smem_u32(const void* p) {
    uint32_t a;
    asm("{ .reg .u64 t; cvta.to.shared.u64 t, %1; cvt.u32.u64 %0, t; }"
        : "=r"(a) : "l"(p));
    return a;
}
__device__ __forceinline__ void ldsm4(uint32_t* r, uint32_t a) {
    asm volatile("ldmatrix.sync.aligned.m8n8.x4.shared.b16 {%0,%1,%2,%3}, [%4];"
                 : "=r"(r[0]), "=r"(r[1]), "=r"(r[2]), "=r"(r[3]) : "r"(a));
}
__device__ __forceinline__ void mma16816(float* d, const uint32_t* a, const uint32_t* b) {
    asm volatile("mma.sync.aligned.m16n8k16.row.col.f32.f16.f16.f32 "
                 "{%0,%1,%2,%3}, {%4,%5,%6,%7}, {%8,%9}, {%0,%1,%2,%3};"
                 : "+f"(d[0]), "+f"(d[1]), "+f"(d[2]), "+f"(d[3])
                 : "r"(a[0]), "r"(a[1]), "r"(a[2]), "r"(a[3]),
                   "r"(b[0]), "r"(b[1]));
}

// ---------------------------------------------------------------------------
// Prologue: 2-way fp16 split of W1^T * 2^11 directly into the m16n8k16 B
// fragment layout the mma consumes, replicating the ldmatrix distribution:
//   reg r of lane holds B[n][k], B[n][k+1] with
//     n = wc*96 + p*16 + (r>=2 ? 8 : 0) + lane/4
//     k = ks*16 + (r&1)*8 + (lane%4)*2
// ---------------------------------------------------------------------------
__global__ void __launch_bounds__(256)
wsplit_kernel(const float* __restrict__ W1)
{
    int idx = blockIdx.x * 256 + threadIdx.x;      // 147456 = 576 * 256
    int lane_r = idx & 127;
    int lane = lane_r >> 2, r = lane_r & 3;
    int rest = idx >> 7;                           // ((ks*4+wc)*2+sbp)*6 + p
    int p = rest % 6; rest /= 6;
    int sbp = rest & 1; rest >>= 1;
    int wc = rest & 3;
    int ks = rest >> 2;

    int n = wc * 96 + p * 16 + ((r >> 1) << 3) + (lane >> 2);
    int k = ks * 16 + ((r & 1) << 3) + ((lane & 3) << 1);

    float x0 = W1[k * HID2 + n] * WSCALE;
    float x1 = W1[(k + 1) * HID2 + n] * WSCALE;
    __half h0, h1;
    if (sbp == 0) {
        h0 = __float2half_rn(x0);
        h1 = __float2half_rn(x1);
    } else {
        h0 = __float2half_rn(x0 - __half2float(__float2half_rn(x0)));
        h1 = __float2half_rn(x1 - __half2float(__float2half_rn(x1)));
    }
    d_Bfrag[idx] = ((uint32_t)__half_as_ushort(h1) << 16) | __half_as_ushort(h0);
}

// no-op launches: keep head_kernel at captured launch slot #4 for ncu
__global__ void dummy_kernel() {}

// ---------------------------------------------------------------------------
// B fragment load: 12 x LDG.128 per warp per k-step, straight to registers.
// uint4 index = ks*1536 + wc*384 + sbp*192 + p*32 + lane  (j = sbp*6 + p)
// ---------------------------------------------------------------------------
__device__ __forceinline__ void loadB(uint4* dst, int ks, uint32_t wbase) {
    const uint4* __restrict__ B4 = (const uint4*)d_Bfrag;
#pragma unroll
    for (int j = 0; j < 12; j++)
        dst[j] = __ldg(&B4[(uint32_t)ks * 1536u + wbase
                           + (uint32_t)(j / 6) * 192u + (uint32_t)(j % 6) * 32u]);
}

// One k-step: 4 ldsm for A (2 splits x 2 m), then 72 MMAs (3 terms).
__device__ __forceinline__ void doKstep(float acc[2][12][4],
                                        const uint32_t aAddr[2][2],
                                        int ks, const uint4* Bv) {
    uint32_t Afr[2][2][4];
#pragma unroll
    for (int s = 0; s < 2; s++)
#pragma unroll
        for (int m = 0; m < 2; m++)
            ldsm4(Afr[s][m], aAddr[s][m] + (uint32_t)ks * 32u);

    // b-split 0: terms a1b1 (sa=0) and a2b1 (sa=1)
#pragma unroll
    for (int sa = 0; sa < 2; sa++)
#pragma unroll
        for (int p = 0; p < 6; p++) {
            const uint32_t* b = (const uint32_t*)&Bv[p];
#pragma unroll
            for (int m = 0; m < 2; m++) {
                mma16816(acc[m][2 * p],     Afr[sa][m], b);
                mma16816(acc[m][2 * p + 1], Afr[sa][m], b + 2);
            }
        }
    // b-split 1: term a1b2 (a2b2 dropped, ~1e-8 rel; validated R10)
#pragma unroll
    for (int p = 0; p < 6; p++) {
        const uint32_t* b = (const uint32_t*)&Bv[6 + p];
#pragma unroll
        for (int m = 0; m < 2; m++) {
            mma16816(acc[m][2 * p],     Afr[0][m], b);
            mma16816(acc[m][2 * p + 1], Afr[0][m], b + 2);
        }
    }
}

// ---------------------------------------------------------------------------
// Head: 64 nodes x 384 cols per CTA; 8 warps (2 M x 4 N), warp tile 32x96.
// 3-term fp16 2x2-split HMMA. B operands LDG'd directly in fragment layout,
// double-buffered in registers -- no smem B, no cp.async, no mainloop barriers.
// Fused b1 + LayerNorm + ReLU + dot(W2) epilogue with 2^-19 descale.
// ---------------------------------------------------------------------------
__global__ void __launch_bounds__(NTHREAD, 1)
head_kernel(const float* __restrict__ h, const float* __restrict__ g,
            const float* __restrict__ b1, const float* __restrict__ lngamma,
            const float* __restrict__ lnbeta, const float* __restrict__ W2,
            const float* __restrict__ b2, float* __restrict__ logits)
{
    extern __shared__ char sm[];
    const uint32_t sb = smem_u32(sm);

    const int tid  = threadIdx.x;
    const int wid  = tid >> 5;
    const int lane = tid & 31;
    const int wr   = wid & 1;            // M-warp (2), 32 rows each
    const int wc   = wid >> 1;           // N-warp (4), 96 cols each
    const int n0   = blockIdx.x * MTILE;
    const float b2v = __ldg(b2);

    // ---- params -> smem ----
    {
        float* par = (float*)(sm + OFF_PAR);
        for (int i = tid; i < HID2; i += NTHREAD) {
            par[i]            = b1[i];
            par[HID2 + i]     = lngamma[i];
            par[2 * HID2 + i] = lnbeta[i];
            par[3 * HID2 + i] = W2[i];
        }
    }

    // ---- A build: x = (h + g[graph]) * 2^8, 2-way fp16 split -> smem ----
    {
        const float2* h2p = (const float2*)h;
        const int gbase = (n0 >> 8) * HID;
        for (int i = tid; i < MTILE * 96; i += NTHREAD) {   // col-pairs
            int row = i / 96, cp = i % 96;
            float2 hv = h2p[(n0 + row) * 96 + cp];
            int c0 = cp * 2;
            float x0 = (hv.x + __ldg(&g[gbase + c0]))     * XSCALE;
            float x1 = (hv.y + __ldg(&g[gbase + c0 + 1])) * XSCALE;

            __half a0 = __float2half_rn(x0), e0 = __float2half_rn(x1);
            float ra = x0 - __half2float(a0), rb = x1 - __half2float(e0);
            __half a1 = __float2half_rn(ra), e1 = __float2half_rn(rb);

            uint32_t p0 = ((uint32_t)__half_as_ushort(e0) << 16) | __half_as_ushort(a0);
            uint32_t p1 = ((uint32_t)__half_as_ushort(e1) << 16) | __half_as_ushort(a1);

            uint32_t off = (uint32_t)row * (A_PITCH * 2) + (uint32_t)c0 * 2u;
            *(uint32_t*)(sm + OFF_A + off)             = p0;
            *(uint32_t*)(sm + OFF_A + A_SPLIT_B + off) = p1;
        }
    }
    __syncthreads();                     // A + params visible; only barrier

    // ---- ldmatrix addresses for A ----
    const int q = lane >> 3;
    const uint32_t aRowByte =
        (uint32_t)(wr * 32 + (lane & 7) + ((q & 1) << 3)) * (A_PITCH * 2);
    const uint32_t aColByte = (uint32_t)((q >> 1) << 3) * 2;
    uint32_t aAddr[2][2];
#pragma unroll
    for (int s = 0; s < 2; s++)
#pragma unroll
        for (int m = 0; m < 2; m++)
            aAddr[s][m] = sb + OFF_A + (uint32_t)s * A_SPLIT_B
                        + aRowByte + (uint32_t)m * 16u * (A_PITCH * 2) + aColByte;

    const uint32_t wbase = (uint32_t)wc * 384u + (uint32_t)lane;

    float acc[2][12][4];
#pragma unroll
    for (int m = 0; m < 2; m++)
#pragma unroll
        for (int nt = 0; nt < 12; nt++)
#pragma unroll
            for (int j = 0; j < 4; j++) acc[m][nt][j] = 0.f;

    // ---- main loop: register double-buffered B, no barriers ----
    uint4 B0[12], B1[12];
    loadB(B0, 0, wbase);
    for (int ks = 0; ks < KSTEPS; ks += 2) {
        loadB(B1, ks + 1, wbase);
        doKstep(acc, aAddr, ks, B0);
        if (ks + 2 < KSTEPS) loadB(B0, ks + 2, wbase);
        doKstep(acc, aAddr, ks + 1, B1);
    }

    // ---- epilogue: descale, +b1, LN stats, LN+ReLU+dot(W2) ----
    const float* par = (const float*)(sm + OFF_PAR);
    float* rs1 = (float*)(sm + OFF_RS1);
    float* rs2 = (float*)(sm + OFF_RS2);
    float* rt  = (float*)(sm + OFF_RT);
    const int l4 = lane >> 2, lm = lane & 3;

#pragma unroll
    for (int m = 0; m < 2; m++)
#pragma unroll
        for (int hf = 0; hf < 2; hf++) {
            float s1 = 0.f, s2 = 0.f;
#pragma unroll
            for (int nt = 0; nt < 12; nt++) {
                const int cb = wc * 96 + nt * 8 + 2 * lm;
                float2 bv = *(const float2*)&par[cb];
                float v0 = acc[m][nt][2 * hf]     * DESCALE + bv.x;
                float v1 = acc[m][nt][2 * hf + 1] * DESCALE + bv.y;
                s1 += v0 + v1; s2 += v0 * v0 + v1 * v1;
            }
            s1 += __shfl_xor_sync(0xffffffffu, s1, 1);
            s1 += __shfl_xor_sync(0xffffffffu, s1, 2);
            s2 += __shfl_xor_sync(0xffffffffu, s2, 1);
            s2 += __shfl_xor_sync(0xffffffffu, s2, 2);
            if (lm == 0) {
                const int row = wr * 32 + m * 16 + hf * 8 + l4;
                rs1[row * 4 + wc] = s1;
                rs2[row * 4 + wc] = s2;
            }
        }
    __syncthreads();

#pragma unroll
    for (int m = 0; m < 2; m++)
#pragma unroll
        for (int hf = 0; hf < 2; hf++) {
            const int row = wr * 32 + m * 16 + hf * 8 + l4;
            const float S1 = rs1[row * 4] + rs1[row * 4 + 1] + rs1[row * 4 + 2] + rs1[row * 4 + 3];
            const float S2 = rs2[row * 4] + rs2[row * 4 + 1] + rs2[row * 4 + 2] + rs2[row * 4 + 3];
            const float mu  = S1 * (1.0f / HID2);
            const float var = S2 * (1.0f / HID2) - mu * mu;
            const float inv = rsqrtf(var + LN_EPS);
            float t = 0.f;
#pragma unroll
            for (int nt = 0; nt < 12; nt++) {
                const int cb = wc * 96 + nt * 8 + 2 * lm;
                float2 bv = *(const float2*)&par[cb];
                float2 gm = *(const float2*)&par[HID2 + cb];
                float2 bt = *(const float2*)&par[2 * HID2 + cb];
                float2 w2 = *(const float2*)&par[3 * HID2 + cb];
                float v0 = acc[m][nt][2 * hf]     * DESCALE + bv.x;
                float v1 = acc[m][nt][2 * hf + 1] * DESCALE + bv.y;
                float z0 = fmaxf((v0 - mu) * inv * gm.x + bt.x, 0.f);
                float z1 = fmaxf((v1 - mu) * inv * gm.y + bt.y, 0.f);
                t += z0 * w2.x + z1 * w2.y;
            }
            t += __shfl_xor_sync(0xffffffffu, t, 1);
            t += __shfl_xor_sync(0xffffffffu, t, 2);
            if (lm == 0) rt[row * 4 + wc] = t;
        }
    __syncthreads();
    if (tid < MTILE)
        logits[n0 + tid] = rt[tid * 4] + rt[tid * 4 + 1] + rt[tid * 4 + 2]
                         + rt[tid * 4 + 3] + b2v;
}

// ---------------------------------------------------------------------------
// Exact per-graph top-k (jax tie semantics); writes packed {keep, logit};
// zeroes touched[].
// ---------------------------------------------------------------------------
__global__ void __launch_bounds__(256)
topk_kernel(const float* __restrict__ logits)
{
    __shared__ float sv[NPG];
    const int node = blockIdx.x * NPG + threadIdx.x;
    const int t = threadIdx.x;
    const float v = logits[node];
    sv[t] = v;
    d_touched[node] = 0;
    __syncthreads();
    int rank = 0;
#pragma unroll 8
    for (int j = 0; j < NPG; j++) {
        const float u = sv[j];
        rank += (u > v) || (u == v && j < t);
    }
    d_klg[node] = make_float2((rank < KKEEP) ? 1.0f : 0.0f, v);
}

// ---------------------------------------------------------------------------
// Edge masking + weights + touched flags (4 edges / thread, packed gathers)
// ---------------------------------------------------------------------------
__global__ void __launch_bounds__(256)
edge_kernel(const int* __restrict__ ei,
            float* __restrict__ em, float* __restrict__ ew)
{
    const int idx = blockIdx.x * 256 + threadIdx.x;
    const int4 s = ((const int4*)ei)[idx];
    const int4 d = ((const int4*)(ei + NEDGE))[idx];

    const float2 sx = d_klg[s.x], dx = d_klg[d.x];
    const float2 sy = d_klg[s.y], dy = d_klg[d.y];
    const float2 sz = d_klg[s.z], dz = d_klg[d.z];
    const float2 sw = d_klg[s.w], dw = d_klg[d.w];

    float4 m, w;
    m.x = sx.x * dx.x;  w.x = (sx.y + dx.y) * m.x;
    m.y = sy.x * dy.x;  w.y = (sy.y + dy.y) * m.y;
    m.z = sz.x * dz.x;  w.z = (sz.y + dz.y) * m.z;
    m.w = sw.x * dw.x;  w.w = (sw.y + dw.y) * m.w;

    ((float4*)em)[idx] = m;
    ((float4*)ew)[idx] = w;

    if (m.x != 0.f) { d_touched[s.x] = 1; d_touched[d.x] = 1; }
    if (m.y != 0.f) { d_touched[s.y] = 1; d_touched[d.y] = 1; }
    if (m.z != 0.f) { d_touched[s.z] = 1; d_touched[d.z] = 1; }
    if (m.w != 0.f) { d_touched[s.w] = 1; d_touched[d.w] = 1; }
}

__global__ void __launch_bounds__(256)
mask_kernel(float* __restrict__ nm)
{
    const int i = blockIdx.x * 256 + threadIdx.x;
    nm[i] = d_touched[i] ? 1.0f : 0.0f;
}

// ---------------------------------------------------------------------------
// Launch: outputs concatenated f32: edge_mask | edge_weight | logits | node_mask
// head_kernel is launch #4 (ncu capture slot).
// ---------------------------------------------------------------------------
extern "C" void kernel_launch(void* const* d_in, const int* in_sizes, int n_in,
                              void* d_out, int out_size)
{
    const float* h       = (const float*)d_in[0];
    const float* g       = (const float*)d_in[1];
    const int*   ei      = (const int*)  d_in[2];
    const float* W1      = (const float*)d_in[3];
    const float* b1      = (const float*)d_in[4];
    const float* lngamma = (const float*)d_in[5];
    const float* lnbeta  = (const float*)d_in[6];
    const float* W2      = (const float*)d_in[7];
    const float* b2      = (const float*)d_in[8];

    float* out = (float*)d_out;
    float* em = out;
    float* ew = out + (size_t)NEDGE;
    float* lg = out + 2 * (size_t)NEDGE;
    float* nm = lg + NODES;

    cudaFuncSetAttribute(head_kernel,
                         cudaFuncAttributeMaxDynamicSharedMemorySize, SMEM_REQ);

    wsplit_kernel<<<576, 256>>>(W1);                        // #1
    dummy_kernel<<<1, 32>>>();                              // #2
    dummy_kernel<<<1, 32>>>();                              // #3
    head_kernel<<<NODES / MTILE, NTHREAD, SMEM_REQ>>>(      // #4  <- ncu slot
        h, g, b1, lngamma, lnbeta, W2, b2, lg);
    topk_kernel<<<BGRAPH, 256>>>(lg);                       // #5
    edge_kernel<<<NEDGE / 1024, 256>>>(ei, em, ew);         // #6
    mask_kernel<<<NODES / 256, 256>>>(nm);                  // #7
}